// round 3
// baseline (speedup 1.0000x reference)
#include <cuda_runtime.h>
#include <cstdint>

#define L    768
#define D    256
#define NT   12
#define SPAN 8

// ---------------- device scratch (static, no allocs) ----------------
__device__ __align__(16) float g_ht[8][L * D];        // ht per span-length diagonal
__device__ __align__(16) float g_z[L * 4 * D];        // z buffer (1024 cols)
__device__ __align__(16) float g_tagsc[8][L * NT];    // tag scores per diagonal (for gold)
__device__ __align__(16) float g_ex[L * NT * SPAN];   // exp(span scores) [i][t2][k]

#define F2U(x) __float_as_uint(x)

__device__ __forceinline__ void mma_tf32(float& c0, float& c1, float& c2, float& c3,
                                         uint32_t a0, uint32_t a1, uint32_t a2, uint32_t a3,
                                         uint32_t b0, uint32_t b1)
{
    asm volatile("mma.sync.aligned.m16n8k8.row.col.f32.tf32.tf32.f32 "
                 "{%0,%1,%2,%3}, {%4,%5,%6,%7}, {%8,%9}, {%0,%1,%2,%3};\n"
                 : "+f"(c0), "+f"(c1), "+f"(c2), "+f"(c3)
                 : "r"(a0), "r"(a1), "r"(a2), "r"(a3), "r"(b0), "r"(b1));
}

__device__ __forceinline__ void cpa16(float* dst, const float* src)
{
    uint32_t d = (uint32_t)__cvta_generic_to_shared(dst);
    asm volatile("cp.async.cg.shared.global [%0], [%1], 16;\n" :: "r"(d), "l"(src));
}
#define CP_COMMIT() asm volatile("cp.async.commit_group;\n")
#define CP_WAIT(n)  asm volatile("cp.async.wait_group %0;\n" :: "n"(n))

// ---------------- h = feats @ Wd^T + bd  (tf32 MMA, cp.async 2-stage) ----------------
// M=768, N=256, K=512. BM=64, BN=32, BK=16, 256 threads (8 warps, warp tile 16x16).
__global__ void __launch_bounds__(256) sgemm_h_tf32(const float* __restrict__ A,
                                                    const float* __restrict__ B,
                                                    const float* __restrict__ bias)
{
    __shared__ __align__(16) float As[2][64 * 20];
    __shared__ __align__(16) float Bs[2][32 * 20];
    const int K = 512;
    const int tid = threadIdx.x;
    const int lane = tid & 31, warp = tid >> 5;
    const int g = lane >> 2, c = lane & 3;
    const int wm = warp & 3, wn = warp >> 2;
    const int m0 = blockIdx.y * 64, n0 = blockIdx.x * 32;

    const int ar = tid >> 2, ac4 = (tid & 3) * 4;     // 256 A chunks (64x16)
    const int bi = tid & 127;
    const int brr = bi >> 2, bc4 = (bi & 3) * 4;      // 128 B chunks (32x16)
    const bool do_b = tid < 128;

    float acc[2][4] = {};

    // prologue: stage 0
    cpa16(&As[0][ar * 20 + ac4], &A[(size_t)(m0 + ar) * K + ac4]);
    if (do_b) cpa16(&Bs[0][brr * 20 + bc4], &B[(size_t)(n0 + brr) * K + bc4]);
    CP_COMMIT();

    for (int step = 0; step < 32; step++) {
        const int s = step & 1;
        if (step < 31) {
            const int k0 = (step + 1) * 16, s2 = s ^ 1;
            cpa16(&As[s2][ar * 20 + ac4], &A[(size_t)(m0 + ar) * K + k0 + ac4]);
            if (do_b) cpa16(&Bs[s2][brr * 20 + bc4], &B[(size_t)(n0 + brr) * K + k0 + bc4]);
            CP_COMMIT();
            CP_WAIT(1);
        } else {
            CP_WAIT(0);
        }
        __syncthreads();
#pragma unroll
        for (int kc = 0; kc < 2; kc++) {
            const int ko = kc * 8 + c;
            const float* p = &As[s][(wm * 16 + g) * 20 + ko];
            uint32_t a0 = F2U(p[0]), a2 = F2U(p[4]);
            uint32_t a1 = F2U(p[160]), a3 = F2U(p[164]);
#pragma unroll
            for (int ni = 0; ni < 2; ni++) {
                const float* pb = &Bs[s][(wn * 16 + ni * 8 + g) * 20 + ko];
                uint32_t b0 = F2U(pb[0]), b1 = F2U(pb[4]);
                mma_tf32(acc[ni][0], acc[ni][1], acc[ni][2], acc[ni][3],
                         a0, a1, a2, a3, b0, b1);
            }
        }
        __syncthreads();
    }
#pragma unroll
    for (int ni = 0; ni < 2; ni++) {
        int col = n0 + wn * 16 + ni * 8 + 2 * c;
        float bv0 = bias[col], bv1 = bias[col + 1];
        int row0 = m0 + wm * 16 + g;
        g_ht[0][(size_t)row0 * 256 + col]           = acc[ni][0] + bv0;
        g_ht[0][(size_t)row0 * 256 + col + 1]       = acc[ni][1] + bv1;
        g_ht[0][(size_t)(row0 + 8) * 256 + col]     = acc[ni][2] + bv0;
        g_ht[0][(size_t)(row0 + 8) * 256 + col + 1] = acc[ni][3] + bv1;
    }
}

// ---------------- dual GEMM: z = l@WL^T + r@WR^T + bias (tf32, cp.async 2-stage) ----
// BM=64(+1 shift row), BN=32, BK=16, 256 threads, grid (32, 12) = 384 CTAs.
__global__ void __launch_bounds__(256) sgemm_dual_tf32(
    const float* __restrict__ Wl, const float* __restrict__ Wr,
    const float* __restrict__ Gl, const float* __restrict__ Gr,
    const float* __restrict__ bl, const float* __restrict__ br,
    const float* __restrict__ bgl, const float* __restrict__ bgr,
    int sl)
{
    const int M = L - sl;
    const float* Aht = g_ht[sl - 1];
    __shared__ __align__(16) float As[2][65 * 20];
    __shared__ __align__(16) float Bsm[2][2][32 * 20];
    const int tid = threadIdx.x;
    const int lane = tid & 31, warp = tid >> 5;
    const int g = lane >> 2, c = lane & 3;
    const int wm = warp & 3, wn = warp >> 2;
    const int m0 = blockIdx.y * 64, n0 = blockIdx.x * 32;
    const float* BLg = (n0 < 256) ? (Wl + (size_t)n0 * 256) : (Gl + (size_t)(n0 - 256) * 256);
    const float* BRg = (n0 < 256) ? (Wr + (size_t)n0 * 256) : (Gr + (size_t)(n0 - 256) * 256);

    const int ar = tid >> 2, ac4 = (tid & 3) * 4;     // 256 of 260 A chunks
    const int bh = tid >> 7, bi = tid & 127;          // half 0 -> BL, half 1 -> BR
    const int brr = bi >> 2, bc4 = (bi & 3) * 4;
    const float* bsrc = bh ? BRg : BLg;

    float acc[2][4] = {};

    // prologue: stage 0
    {
        cpa16(&As[0][ar * 20 + ac4], &Aht[(size_t)(m0 + ar) * 256 + ac4]);
        if (tid < 4) cpa16(&As[0][64 * 20 + tid * 4], &Aht[(size_t)(m0 + 64) * 256 + tid * 4]);
        cpa16(&Bsm[0][bh][brr * 20 + bc4], &bsrc[(size_t)brr * 256 + bc4]);
        CP_COMMIT();
    }

    for (int step = 0; step < 16; step++) {
        const int s = step & 1;
        if (step < 15) {
            const int k0 = (step + 1) * 16, s2 = s ^ 1;
            cpa16(&As[s2][ar * 20 + ac4], &Aht[(size_t)(m0 + ar) * 256 + k0 + ac4]);
            if (tid < 4) cpa16(&As[s2][64 * 20 + tid * 4],
                               &Aht[(size_t)(m0 + 64) * 256 + k0 + tid * 4]);
            cpa16(&Bsm[s2][bh][brr * 20 + bc4], &bsrc[(size_t)brr * 256 + k0 + bc4]);
            CP_COMMIT();
            CP_WAIT(1);
        } else {
            CP_WAIT(0);
        }
        __syncthreads();
#pragma unroll
        for (int kc = 0; kc < 2; kc++) {
            const int ko = kc * 8 + c;
            const float* p = &As[s][(wm * 16 + g) * 20 + ko];
            uint32_t a0 = F2U(p[0]),   a2 = F2U(p[4]);
            uint32_t a1 = F2U(p[160]), a3 = F2U(p[164]);
            const float* q = p + 20;                  // shifted one row: r operand
            uint32_t r0 = F2U(q[0]),   r2 = F2U(q[4]);
            uint32_t r1 = F2U(q[160]), r3 = F2U(q[164]);
#pragma unroll
            for (int ni = 0; ni < 2; ni++) {
                const float* pl = &Bsm[s][0][(wn * 16 + ni * 8 + g) * 20 + ko];
                uint32_t b0 = F2U(pl[0]), b1 = F2U(pl[4]);
                const float* pr = &Bsm[s][1][(wn * 16 + ni * 8 + g) * 20 + ko];
                uint32_t d0 = F2U(pr[0]), d1 = F2U(pr[4]);
                mma_tf32(acc[ni][0], acc[ni][1], acc[ni][2], acc[ni][3],
                         a0, a1, a2, a3, b0, b1);
                mma_tf32(acc[ni][0], acc[ni][1], acc[ni][2], acc[ni][3],
                         r0, r1, r2, r3, d0, d1);
            }
        }
        __syncthreads();
    }
    // epilogue: + (bl+br | bgl+bgr), masked store rows < M
#pragma unroll
    for (int ni = 0; ni < 2; ni++) {
        int col = n0 + wn * 16 + ni * 8 + 2 * c;
        float bv0, bv1;
        if (col < 256) { bv0 = bl[col] + br[col];               bv1 = bl[col + 1] + br[col + 1]; }
        else           { bv0 = bgl[col - 256] + bgr[col - 256]; bv1 = bgl[col - 255] + bgr[col - 255]; }
        int row0 = m0 + wm * 16 + g;
        if (row0 < M) {
            g_z[(size_t)row0 * 1024 + col]     = acc[ni][0] + bv0;
            g_z[(size_t)row0 * 1024 + col + 1] = acc[ni][1] + bv1;
        }
        int row1 = row0 + 8;
        if (row1 < M) {
            g_z[(size_t)row1 * 1024 + col]     = acc[ni][2] + bv0;
            g_z[(size_t)row1 * 1024 + col + 1] = acc[ni][3] + bv1;
        }
    }
}

// ---------------- gate epilogue: ht_sl = w0*h_hat + w1*l + w2*r ----------------
__global__ void gate_kernel(int sl)
{
    const int M = L - sl;
    int idx = blockIdx.x * 256 + threadIdx.x;
    if (idx >= M * D) return;
    int pos = idx >> 8;
    int d = idx & 255;
    const float* zp = g_z + (size_t)pos * 1024;
    float hv = zp[d];
    float g0 = zp[256 + d], g1 = zp[512 + d], g2 = zp[768 + d];
    float hh = 4.f / (1.f + __expf(-hv)) - 2.f;
    float mx = fmaxf(g0, fmaxf(g1, g2));
    float e0 = __expf(g0 - mx), e1 = __expf(g1 - mx), e2 = __expf(g2 - mx);
    float inv = 1.f / (e0 + e1 + e2);
    float lft = g_ht[sl - 1][idx];
    float rgt = g_ht[sl - 1][idx + D];
    g_ht[sl][idx] = (e0 * hh + e1 * lft + e2 * rgt) * inv;
}

// ---------------- tag scores + exp-gather into ex layout ----------------
__global__ void tagsc_kernel(const float* __restrict__ Wt, const float* __restrict__ bt)
{
    __shared__ float sWt[NT * D];
    int tid = threadIdx.x;
    for (int i = tid; i < NT * D; i += 256) sWt[i] = Wt[i];
    __syncthreads();
    int warp = tid >> 5, lane = tid & 31;
    int gw = blockIdx.x * 8 + warp;        // 0..6143
    int sl = gw / L;
    int pos = gw - sl * L;
    if (pos + sl >= L) return;
    const float* hp = g_ht[sl] + (size_t)pos * D;
    float4 h0 = *(const float4*)&hp[lane * 8];
    float4 h1 = *(const float4*)&hp[lane * 8 + 4];
    float hv[8] = {h0.x,h0.y,h0.z,h0.w,h1.x,h1.y,h1.z,h1.w};
    int i_end = pos + sl, k = 7 - sl;
#pragma unroll
    for (int t = 0; t < NT; t++) {
        const float* wp = &sWt[t * D + lane * 8];
        float4 w0 = *(const float4*)wp;
        float4 w1 = *(const float4*)(wp + 4);
        float s = hv[0]*w0.x + hv[1]*w0.y + hv[2]*w0.z + hv[3]*w0.w
                + hv[4]*w1.x + hv[5]*w1.y + hv[6]*w1.z + hv[7]*w1.w;
#pragma unroll
        for (int o = 16; o; o >>= 1) s += __shfl_xor_sync(0xffffffffu, s, o);
        if (lane == 0) {
            float val = s + bt[t];
            g_tagsc[sl][pos * NT + t] = val;
            g_ex[((size_t)i_end * NT + t) * SPAN + k] = __expf(val);
        }
    }
}

// ---------------- gold score + exp-domain forward scan (single warp) ----------------
__global__ void forward_kernel(const float* __restrict__ trans,
                               const float* __restrict__ bt,
                               const int* __restrict__ tags,
                               float* __restrict__ out)
{
    const int lane = threadIdx.x;

    // ---- gold score (96 spans) ----
    float gold = 0.f;
    for (int s = lane; s < 96; s += 32) {
        int i  = tags[s * 4 + 0];
        int j  = tags[s * 4 + 1];
        int pr = tags[s * 4 + 2];
        int t  = tags[s * 4 + 3];
        int sl = j - i;
        float base;
        if (sl >= 0 && sl < SPAN && i >= 0 && i + sl < L)
            base = g_tagsc[sl][i * NT + t];
        else
            base = bt[t];
        gold += base + trans[pr * NT + t];
    }
#pragma unroll
    for (int o = 16; o; o >>= 1) gold += __shfl_xor_sync(0xffffffffu, gold, o);

    // ---- zero never-written ex slots (i<7, k<7-i) ----
    for (int idx = lane; idx < 7 * NT * SPAN; idx += 32) {
        int i = idx / (NT * SPAN);
        int rem = idx - i * (NT * SPAN);
        int t = rem >> 3, k = rem & 7;
        if (k < 7 - i) g_ex[((size_t)i * NT + t) * SPAN + k] = 0.f;
    }
    __syncwarp();

    // ---- setup ----
    const int t2 = lane < NT ? lane : NT - 1;
    float Texp[NT];
#pragma unroll
    for (int t1 = 0; t1 < NT; t1++) Texp[t1] = expf(trans[t1 * NT + t2]);
    float B[8] = {0.f, 0.f, 0.f, 0.f, 0.f, 0.f, 0.f, Texp[10]};
    float S = 0.f;

    const float4* exbase = (const float4*)(g_ex + (size_t)t2 * SPAN);
    float4 curA[8], curB[8], nxtA[8], nxtB[8];
#pragma unroll
    for (int u = 0; u < 8; u++) {
        curA[u] = exbase[(size_t)u * 24];
        curB[u] = exbase[(size_t)u * 24 + 1];
    }

    float v = 0.f;
    for (int b = 0; b < 96; b++) {
        if (b < 95) {
            const float4* nb = exbase + (size_t)(b + 1) * 8 * 24;
#pragma unroll
            for (int u = 0; u < 8; u++) {
                nxtA[u] = nb[(size_t)u * 24];
                nxtB[u] = nb[(size_t)u * 24 + 1];
            }
        }
#pragma unroll
        for (int u = 0; u < 8; u++) {
            float e0 = curA[u].x, e1 = curA[u].y, e2 = curA[u].z, e3 = curA[u].w;
            float e4 = curB[u].x, e5 = curB[u].y, e6 = curB[u].z, e7 = curB[u].w;
            // v = sum_k e_k * B[(u+k)&7]; keep the B[u-dependent] term (k=7) last
            float v01 = fmaf(e1, B[(u + 1) & 7], e0 * B[(u + 0) & 7]);
            float v23 = fmaf(e3, B[(u + 3) & 7], e2 * B[(u + 2) & 7]);
            float v45 = fmaf(e5, B[(u + 5) & 7], e4 * B[(u + 4) & 7]);
            float v6  = e6 * B[(u + 6) & 7];
            float vp  = ((v01 + v23) + (v45 + v6));
            v = fmaf(e7, B[(u + 7) & 7], vp);
            // B'[t2] = sum_t1 Texp[t1] * v[t1]  (tree reduction over 12 products)
            float p0  = Texp[0]  * __shfl_sync(0xffffffffu, v, 0);
            float p1  = Texp[1]  * __shfl_sync(0xffffffffu, v, 1);
            float p2  = Texp[2]  * __shfl_sync(0xffffffffu, v, 2);
            float p3  = Texp[3]  * __shfl_sync(0xffffffffu, v, 3);
            float p4  = Texp[4]  * __shfl_sync(0xffffffffu, v, 4);
            float p5  = Texp[5]  * __shfl_sync(0xffffffffu, v, 5);
            float p6  = Texp[6]  * __shfl_sync(0xffffffffu, v, 6);
            float p7  = Texp[7]  * __shfl_sync(0xffffffffu, v, 7);
            float p8  = Texp[8]  * __shfl_sync(0xffffffffu, v, 8);
            float p9  = Texp[9]  * __shfl_sync(0xffffffffu, v, 9);
            float p10 = Texp[10] * __shfl_sync(0xffffffffu, v, 10);
            float p11 = Texp[11] * __shfl_sync(0xffffffffu, v, 11);
            B[u] = (((p0 + p1) + (p2 + p3)) + ((p4 + p5) + (p6 + p7)))
                 + ((p8 + p9) + (p10 + p11));
        }
        if (b < 95) {
            float cc = __shfl_sync(0xffffffffu, v, 0);
            float inv = 1.f / cc;
#pragma unroll
            for (int k = 0; k < 8; k++) B[k] *= inv;
            S += logf(cc);
#pragma unroll
            for (int u = 0; u < 8; u++) { curA[u] = nxtA[u]; curB[u] = nxtB[u]; }
        }
    }

    float contrib = (lane < 11) ? (S + logf(v)) : 0.f;
#pragma unroll
    for (int o = 16; o; o >>= 1) contrib += __shfl_xor_sync(0xffffffffu, contrib, o);
    if (lane == 0) out[0] = contrib - gold;
}

// ---------------- launch ----------------
extern "C" void kernel_launch(void* const* d_in, const int* in_sizes, int n_in,
                              void* d_out, int out_size)
{
    const float* feats = (const float*)d_in[0];
    const int*   tags  = (const int*)d_in[1];
    const float* Wd    = (const float*)d_in[2];
    const float* bd    = (const float*)d_in[3];
    const float* Wl    = (const float*)d_in[4];
    const float* bl    = (const float*)d_in[5];
    const float* Wr    = (const float*)d_in[6];
    const float* br    = (const float*)d_in[7];
    const float* Gl    = (const float*)d_in[8];
    const float* bgl   = (const float*)d_in[9];
    const float* Gr    = (const float*)d_in[10];
    const float* bgr   = (const float*)d_in[11];
    const float* Wt    = (const float*)d_in[12];
    const float* bt    = (const float*)d_in[13];
    const float* trans = (const float*)d_in[14];
    float* out = (float*)d_out;

    sgemm_h_tf32<<<dim3(8, 12), 256>>>(feats, Wd, bd);

    for (int sl = 1; sl <= 7; sl++) {
        int M = L - sl;
        sgemm_dual_tf32<<<dim3(32, 12), 256>>>(Wl, Wr, Gl, Gr, bl, br, bgl, bgr, sl);
        gate_kernel<<<(M * D + 255) / 256, 256>>>(sl);
    }

    tagsc_kernel<<<L, 256>>>(Wt, bt);
    forward_kernel<<<1, 32>>>(trans, bt, tags, out);
}

// round 4
// speedup vs baseline: 1.5897x; 1.5897x over previous
#include <cuda_runtime.h>
#include <cstdint>

#define L    768
#define D    256
#define NT   12
#define SPAN 8

// ---------------- device scratch (static, no allocs) ----------------
__device__ __align__(16) float g_ht[8][L * D];        // ht per span-length diagonal
__device__ __align__(16) float g_BsL[1024 * 256];     // stacked interleaved [Wl|Gl], col'=4d+j
__device__ __align__(16) float g_BsR[1024 * 256];     // stacked interleaved [Wr|Gr]
__device__ __align__(16) float g_biasS[1024];         // stacked bias (bl+br | bgl+bgr)
__device__ __align__(16) float g_tagsc[8][L * NT];    // tag scores per diagonal (for gold)
__device__ __align__(16) float g_ex[L * NT * SPAN];   // exp(span scores) [i][t2][k]

#define F2U(x) __float_as_uint(x)

__device__ __forceinline__ void mma_tf32(float& c0, float& c1, float& c2, float& c3,
                                         uint32_t a0, uint32_t a1, uint32_t a2, uint32_t a3,
                                         uint32_t b0, uint32_t b1)
{
    asm volatile("mma.sync.aligned.m16n8k8.row.col.f32.tf32.tf32.f32 "
                 "{%0,%1,%2,%3}, {%4,%5,%6,%7}, {%8,%9}, {%0,%1,%2,%3};\n"
                 : "+f"(c0), "+f"(c1), "+f"(c2), "+f"(c3)
                 : "r"(a0), "r"(a1), "r"(a2), "r"(a3), "r"(b0), "r"(b1));
}

__device__ __forceinline__ void cpa16(float* dst, const float* src)
{
    uint32_t d = (uint32_t)__cvta_generic_to_shared(dst);
    asm volatile("cp.async.cg.shared.global [%0], [%1], 16;\n" :: "r"(d), "l"(src));
}
#define CP_COMMIT() asm volatile("cp.async.commit_group;\n")
#define CP_WAIT(n)  asm volatile("cp.async.wait_group %0;\n" :: "n"(n))

// ---------------- prep: build stacked interleaved B + bias ----------------
// col' = 4*d + j : j==0 -> Wl/Wr row d (h_hat path); j in 1..3 -> Gl/Gr row (j-1)*256+d.
__global__ void prep_kernel(const float* __restrict__ Wl, const float* __restrict__ Wr,
                            const float* __restrict__ Gl, const float* __restrict__ Gr,
                            const float* __restrict__ bl, const float* __restrict__ br,
                            const float* __restrict__ bgl, const float* __restrict__ bgr)
{
    int idx = blockIdx.x * 256 + threadIdx.x;      // over 1024 rows * 64 float4
    int row = idx >> 6, k = (idx & 63) * 4;
    int d = row >> 2, j = row & 3;
    int srcrow = (j == 0) ? d : ((j - 1) * 256 + d);
    const float* sl4 = (j == 0) ? Wl : Gl;
    const float* sr4 = (j == 0) ? Wr : Gr;
    *(float4*)&g_BsL[(size_t)row * 256 + k] = *(const float4*)&sl4[(size_t)srcrow * 256 + k];
    *(float4*)&g_BsR[(size_t)row * 256 + k] = *(const float4*)&sr4[(size_t)srcrow * 256 + k];
    if (idx < 1024) {
        int dd = idx >> 2, jj = idx & 3;
        g_biasS[idx] = (jj == 0) ? (bl[dd] + br[dd])
                                 : (bgl[(jj - 1) * 256 + dd] + bgr[(jj - 1) * 256 + dd]);
    }
}

// ---------------- h = feats @ Wd^T + bd  (tf32 MMA, 3-stage cp.async) ----------------
// M=768, N=256, K=512. BM=64, BN=32, BK=16, 256 threads, grid (8,12).
__global__ void __launch_bounds__(256) sgemm_h_tf32(const float* __restrict__ A,
                                                    const float* __restrict__ B,
                                                    const float* __restrict__ bias)
{
    __shared__ __align__(16) float As[3][64 * 20];
    __shared__ __align__(16) float Bs[3][32 * 20];
    const int K = 512, NSTEP = 32;
    const int tid = threadIdx.x;
    const int lane = tid & 31, warp = tid >> 5;
    const int g = lane >> 2, c = lane & 3;
    const int wm = warp & 3, wn = warp >> 2;
    const int m0 = blockIdx.y * 64, n0 = blockIdx.x * 32;

    const int ar = tid >> 2, ac4 = (tid & 3) * 4;
    const int bi = tid & 127;
    const int brr = bi >> 2, bc4 = (bi & 3) * 4;
    const bool do_b = tid < 128;

    float acc[2][4] = {};

#pragma unroll
    for (int st = 0; st < 2; st++) {
        const int k0 = st * 16;
        cpa16(&As[st][ar * 20 + ac4], &A[(size_t)(m0 + ar) * K + k0 + ac4]);
        if (do_b) cpa16(&Bs[st][brr * 20 + bc4], &B[(size_t)(n0 + brr) * K + k0 + bc4]);
        CP_COMMIT();
    }

    for (int step = 0; step < NSTEP; step++) {
        const int s = step % 3;
        if (step + 2 < NSTEP) {
            CP_WAIT(1);
            __syncthreads();
            const int k0 = (step + 2) * 16, s2 = (step + 2) % 3;
            cpa16(&As[s2][ar * 20 + ac4], &A[(size_t)(m0 + ar) * K + k0 + ac4]);
            if (do_b) cpa16(&Bs[s2][brr * 20 + bc4], &B[(size_t)(n0 + brr) * K + k0 + bc4]);
            CP_COMMIT();
        } else {
            CP_WAIT(0);
            __syncthreads();
        }
#pragma unroll
        for (int kc = 0; kc < 2; kc++) {
            const int ko = kc * 8 + c;
            const float* p = &As[s][(wm * 16 + g) * 20 + ko];
            uint32_t a0 = F2U(p[0]),   a2 = F2U(p[4]);
            uint32_t a1 = F2U(p[160]), a3 = F2U(p[164]);
#pragma unroll
            for (int ni = 0; ni < 2; ni++) {
                const float* pb = &Bs[s][(wn * 16 + ni * 8 + g) * 20 + ko];
                uint32_t b0 = F2U(pb[0]), b1 = F2U(pb[4]);
                mma_tf32(acc[ni][0], acc[ni][1], acc[ni][2], acc[ni][3],
                         a0, a1, a2, a3, b0, b1);
            }
        }
    }
#pragma unroll
    for (int ni = 0; ni < 2; ni++) {
        int col = n0 + wn * 16 + ni * 8 + 2 * c;
        float bv0 = bias[col], bv1 = bias[col + 1];
        int row0 = m0 + wm * 16 + g;
        g_ht[0][(size_t)row0 * 256 + col]           = acc[ni][0] + bv0;
        g_ht[0][(size_t)row0 * 256 + col + 1]       = acc[ni][1] + bv1;
        g_ht[0][(size_t)(row0 + 8) * 256 + col]     = acc[ni][2] + bv0;
        g_ht[0][(size_t)(row0 + 8) * 256 + col + 1] = acc[ni][3] + bv1;
    }
}

// ---------------- fused dual GEMM + gate -> ht[sl] directly ----------------
// z(col'=4d+j) = l@BsL[col']+ r@BsR[col'] + biasS ; gate applied in epilogue.
// BM=64(+1 shift row), BN=32, BK=16, 3-stage, 256 threads, grid (32, 12).
__global__ void __launch_bounds__(256) fused_dual_gate(int sl)
{
    const int M = L - sl;
    const float* Aht = g_ht[sl - 1];
    float* htout = g_ht[sl];
    __shared__ __align__(16) float As[3][65 * 20];
    __shared__ __align__(16) float Bsm[3][2][32 * 20];
    const int NSTEP = 16;
    const int tid = threadIdx.x;
    const int lane = tid & 31, warp = tid >> 5;
    const int g = lane >> 2, c = lane & 3;
    const int wm = warp & 3, wn = warp >> 2;
    const int m0 = blockIdx.y * 64, n0 = blockIdx.x * 32;

    const int ar = tid >> 2, ac4 = (tid & 3) * 4;
    const int bh = tid >> 7, bi = tid & 127;
    const int brr = bi >> 2, bc4 = (bi & 3) * 4;
    const float* bsrc = (bh ? g_BsR : g_BsL) + (size_t)n0 * 256;

    float acc[2][4] = {};

#pragma unroll
    for (int st = 0; st < 2; st++) {
        const int k0 = st * 16;
        cpa16(&As[st][ar * 20 + ac4], &Aht[(size_t)(m0 + ar) * 256 + k0 + ac4]);
        if (tid < 4) cpa16(&As[st][64 * 20 + tid * 4],
                           &Aht[(size_t)(m0 + 64) * 256 + k0 + tid * 4]);
        cpa16(&Bsm[st][bh][brr * 20 + bc4], &bsrc[(size_t)brr * 256 + k0 + bc4]);
        CP_COMMIT();
    }

    for (int step = 0; step < NSTEP; step++) {
        const int s = step % 3;
        if (step + 2 < NSTEP) {
            CP_WAIT(1);
            __syncthreads();
            const int k0 = (step + 2) * 16, s2 = (step + 2) % 3;
            cpa16(&As[s2][ar * 20 + ac4], &Aht[(size_t)(m0 + ar) * 256 + k0 + ac4]);
            if (tid < 4) cpa16(&As[s2][64 * 20 + tid * 4],
                               &Aht[(size_t)(m0 + 64) * 256 + k0 + tid * 4]);
            cpa16(&Bsm[s2][bh][brr * 20 + bc4], &bsrc[(size_t)brr * 256 + k0 + bc4]);
            CP_COMMIT();
        } else {
            CP_WAIT(0);
            __syncthreads();
        }
#pragma unroll
        for (int kc = 0; kc < 2; kc++) {
            const int ko = kc * 8 + c;
            const float* p = &As[s][(wm * 16 + g) * 20 + ko];
            uint32_t a0 = F2U(p[0]),   a2 = F2U(p[4]);
            uint32_t a1 = F2U(p[160]), a3 = F2U(p[164]);
            const float* q = p + 20;                  // shifted one row: r operand
            uint32_t r0 = F2U(q[0]),   r2 = F2U(q[4]);
            uint32_t r1 = F2U(q[160]), r3 = F2U(q[164]);
#pragma unroll
            for (int ni = 0; ni < 2; ni++) {
                const float* pl = &Bsm[s][0][(wn * 16 + ni * 8 + g) * 20 + ko];
                uint32_t b0 = F2U(pl[0]), b1 = F2U(pl[4]);
                const float* pr = &Bsm[s][1][(wn * 16 + ni * 8 + g) * 20 + ko];
                uint32_t d0 = F2U(pr[0]), d1 = F2U(pr[4]);
                mma_tf32(acc[ni][0], acc[ni][1], acc[ni][2], acc[ni][3],
                         a0, a1, a2, a3, b0, b1);
                mma_tf32(acc[ni][0], acc[ni][1], acc[ni][2], acc[ni][3],
                         r0, r1, r2, r3, d0, d1);
            }
        }
    }

    // ---- fused gate epilogue ----
    // even lane c holds cols 4d,4d+1 (h, g0); partner (c^1) holds 4d+2,4d+3 (g1, g2).
#pragma unroll
    for (int ni = 0; ni < 2; ni++) {
        int colb = n0 + wn * 16 + ni * 8 + 2 * c;
        float b0 = g_biasS[colb], b1 = g_biasS[colb + 1];
        float z00 = acc[ni][0] + b0, z01 = acc[ni][1] + b1;   // row0
        float z10 = acc[ni][2] + b0, z11 = acc[ni][3] + b1;   // row1
        float w00 = __shfl_xor_sync(0xffffffffu, z00, 1);
        float w01 = __shfl_xor_sync(0xffffffffu, z01, 1);
        float w10 = __shfl_xor_sync(0xffffffffu, z10, 1);
        float w11 = __shfl_xor_sync(0xffffffffu, z11, 1);
        if ((c & 1) == 0) {
            int d = colb >> 2;
            int row0 = m0 + wm * 16 + g;
#pragma unroll
            for (int rr = 0; rr < 2; rr++) {
                int row = row0 + rr * 8;
                if (row < M) {
                    float zh  = rr ? z10 : z00;
                    float zg0 = rr ? z11 : z01;
                    float zg1 = rr ? w10 : w00;
                    float zg2 = rr ? w11 : w01;
                    float lft = Aht[(size_t)row * 256 + d];
                    float rgt = Aht[(size_t)(row + 1) * 256 + d];
                    float hh = 4.f / (1.f + __expf(-zh)) - 2.f;
                    float mx = fmaxf(zg0, fmaxf(zg1, zg2));
                    float e0 = __expf(zg0 - mx), e1 = __expf(zg1 - mx), e2 = __expf(zg2 - mx);
                    float inv = 1.f / (e0 + e1 + e2);
                    htout[(size_t)row * 256 + d] = (e0 * hh + e1 * lft + e2 * rgt) * inv;
                }
            }
        }
    }
}

// ---------------- tag scores + exp-gather into ex layout ----------------
__global__ void tagsc_kernel(const float* __restrict__ Wt, const float* __restrict__ bt)
{
    __shared__ float sWt[NT * D];
    int tid = threadIdx.x;
    for (int i = tid; i < NT * D; i += 256) sWt[i] = Wt[i];
    __syncthreads();
    int warp = tid >> 5, lane = tid & 31;
    int gw = blockIdx.x * 8 + warp;        // 0..6143
    int sl = gw / L;
    int pos = gw - sl * L;
    if (pos + sl >= L) return;
    const float* hp = g_ht[sl] + (size_t)pos * D;
    float4 h0 = *(const float4*)&hp[lane * 8];
    float4 h1 = *(const float4*)&hp[lane * 8 + 4];
    float hv[8] = {h0.x,h0.y,h0.z,h0.w,h1.x,h1.y,h1.z,h1.w};
    int i_end = pos + sl, k = 7 - sl;
#pragma unroll
    for (int t = 0; t < NT; t++) {
        const float* wp = &sWt[t * D + lane * 8];
        float4 w0 = *(const float4*)wp;
        float4 w1 = *(const float4*)(wp + 4);
        float s = hv[0]*w0.x + hv[1]*w0.y + hv[2]*w0.z + hv[3]*w0.w
                + hv[4]*w1.x + hv[5]*w1.y + hv[6]*w1.z + hv[7]*w1.w;
#pragma unroll
        for (int o = 16; o; o >>= 1) s += __shfl_xor_sync(0xffffffffu, s, o);
        if (lane == 0) {
            float val = s + bt[t];
            g_tagsc[sl][pos * NT + t] = val;
            g_ex[((size_t)i_end * NT + t) * SPAN + k] = __expf(val);
        }
    }
}

// ---------------- gold score + exp-domain forward scan (single warp) ----------------
// (round-2 version, verbatim — known good)
__global__ void forward_kernel(const float* __restrict__ trans,
                               const float* __restrict__ bt,
                               const int* __restrict__ tags,
                               float* __restrict__ out)
{
    const int lane = threadIdx.x;

    float gold = 0.f;
    for (int s = lane; s < 96; s += 32) {
        int i  = tags[s * 4 + 0];
        int j  = tags[s * 4 + 1];
        int pr = tags[s * 4 + 2];
        int t  = tags[s * 4 + 3];
        int sl = j - i;
        float base;
        if (sl >= 0 && sl < SPAN && i >= 0 && i + sl < L)
            base = g_tagsc[sl][i * NT + t];
        else
            base = bt[t];
        gold += base + trans[pr * NT + t];
    }
#pragma unroll
    for (int o = 16; o; o >>= 1) gold += __shfl_xor_sync(0xffffffffu, gold, o);

    for (int idx = lane; idx < 7 * NT * SPAN; idx += 32) {
        int i = idx / (NT * SPAN);
        int rem = idx - i * (NT * SPAN);
        int t = rem >> 3, k = rem & 7;
        if (k < 7 - i) g_ex[((size_t)i * NT + t) * SPAN + k] = 0.f;
    }
    __syncwarp();

    const int t2 = lane < NT ? lane : NT - 1;
    float Texp[NT];
#pragma unroll
    for (int t1 = 0; t1 < NT; t1++) Texp[t1] = expf(trans[t1 * NT + t2]);
    float B[8] = {0.f, 0.f, 0.f, 0.f, 0.f, 0.f, 0.f, Texp[10]};
    float S = 0.f;

    const float4* exbase = (const float4*)(g_ex + (size_t)t2 * SPAN);
    float4 curA[8], curB[8], nxtA[8], nxtB[8];
#pragma unroll
    for (int u = 0; u < 8; u++) {
        curA[u] = exbase[(size_t)u * 24];
        curB[u] = exbase[(size_t)u * 24 + 1];
    }

    float v = 0.f;
    for (int b = 0; b < 96; b++) {
        if (b < 95) {
            const float4* nb = exbase + (size_t)(b + 1) * 8 * 24;
#pragma unroll
            for (int u = 0; u < 8; u++) {
                nxtA[u] = nb[(size_t)u * 24];
                nxtB[u] = nb[(size_t)u * 24 + 1];
            }
        }
#pragma unroll
        for (int u = 0; u < 8; u++) {
            float e0 = curA[u].x, e1 = curA[u].y, e2 = curA[u].z, e3 = curA[u].w;
            float e4 = curB[u].x, e5 = curB[u].y, e6 = curB[u].z, e7 = curB[u].w;
            float v01 = fmaf(e1, B[(u + 1) & 7], e0 * B[(u + 0) & 7]);
            float v23 = fmaf(e3, B[(u + 3) & 7], e2 * B[(u + 2) & 7]);
            float v45 = fmaf(e5, B[(u + 5) & 7], e4 * B[(u + 4) & 7]);
            float v67 = fmaf(e7, B[(u + 7) & 7], e6 * B[(u + 6) & 7]);
            v = (v01 + v23) + (v45 + v67);
            float bnA = 0.f, bnB = 0.f;
#pragma unroll
            for (int t1 = 0; t1 < 6; t1++) {
                bnA = fmaf(Texp[t1],     __shfl_sync(0xffffffffu, v, t1),     bnA);
                bnB = fmaf(Texp[t1 + 6], __shfl_sync(0xffffffffu, v, t1 + 6), bnB);
            }
            B[u] = bnA + bnB;
        }
        if (b < 95) {
            float cc = __shfl_sync(0xffffffffu, v, 0);
            float inv = 1.f / cc;
#pragma unroll
            for (int k = 0; k < 8; k++) B[k] *= inv;
            S += logf(cc);
#pragma unroll
            for (int u = 0; u < 8; u++) { curA[u] = nxtA[u]; curB[u] = nxtB[u]; }
        }
    }

    float contrib = (lane < 11) ? (S + logf(v)) : 0.f;
#pragma unroll
    for (int o = 16; o; o >>= 1) contrib += __shfl_xor_sync(0xffffffffu, contrib, o);
    if (lane == 0) out[0] = contrib - gold;
}

// ---------------- launch ----------------
extern "C" void kernel_launch(void* const* d_in, const int* in_sizes, int n_in,
                              void* d_out, int out_size)
{
    const float* feats = (const float*)d_in[0];
    const int*   tags  = (const int*)d_in[1];
    const float* Wd    = (const float*)d_in[2];
    const float* bd    = (const float*)d_in[3];
    const float* Wl    = (const float*)d_in[4];
    const float* bl    = (const float*)d_in[5];
    const float* Wr    = (const float*)d_in[6];
    const float* br    = (const float*)d_in[7];
    const float* Gl    = (const float*)d_in[8];
    const float* bgl   = (const float*)d_in[9];
    const float* Gr    = (const float*)d_in[10];
    const float* bgr   = (const float*)d_in[11];
    const float* Wt    = (const float*)d_in[12];
    const float* bt    = (const float*)d_in[13];
    const float* trans = (const float*)d_in[14];
    float* out = (float*)d_out;

    prep_kernel<<<256, 256>>>(Wl, Wr, Gl, Gr, bl, br, bgl, bgr);
    sgemm_h_tf32<<<dim3(8, 12), 256>>>(feats, Wd, bd);

    for (int sl = 1; sl <= 7; sl++)
        fused_dual_gate<<<dim3(32, 12), 256>>>(sl);

    tagsc_kernel<<<L, 256>>>(Wt, bt);
    forward_kernel<<<1, 32>>>(trans, bt, tags, out);
}

// round 5
// speedup vs baseline: 1.6586x; 1.0434x over previous
#include <cuda_runtime.h>
#include <cstdint>

#define L    768
#define D    256
#define NT   12
#define SPAN 8
#define NCTA 384

// ---------------- device scratch (static, no allocs) ----------------
__device__ __align__(16) float g_ht[8][L * D];        // ht per span-length diagonal
__device__ __align__(16) float g_BsL[1024 * 256];     // stacked interleaved [Wl|Gl], col'=4d+j
__device__ __align__(16) float g_BsR[1024 * 256];     // stacked interleaved [Wr|Gr]
__device__ __align__(16) float g_biasS[1024];         // stacked bias
__device__ __align__(16) float g_tagsc[8][L * NT];    // tag scores per diagonal (for gold)
__device__ __align__(16) float g_ex[L * NT * SPAN];   // exp(span scores) [i][t2][k]
__device__ unsigned g_cnt;                            // grid barrier state (zero-init)
__device__ unsigned g_gen;

#define F2U(x) __float_as_uint(x)

__device__ __forceinline__ void mma_tf32(float& c0, float& c1, float& c2, float& c3,
                                         uint32_t a0, uint32_t a1, uint32_t a2, uint32_t a3,
                                         uint32_t b0, uint32_t b1)
{
    asm volatile("mma.sync.aligned.m16n8k8.row.col.f32.tf32.tf32.f32 "
                 "{%0,%1,%2,%3}, {%4,%5,%6,%7}, {%8,%9}, {%0,%1,%2,%3};\n"
                 : "+f"(c0), "+f"(c1), "+f"(c2), "+f"(c3)
                 : "r"(a0), "r"(a1), "r"(a2), "r"(a3), "r"(b0), "r"(b1));
}

__device__ __forceinline__ void cpa16(float* dst, const float* src)
{
    uint32_t d = (uint32_t)__cvta_generic_to_shared(dst);
    asm volatile("cp.async.cg.shared.global [%0], [%1], 16;\n" :: "r"(d), "l"(src));
}
#define CP_COMMIT() asm volatile("cp.async.commit_group;\n")
#define CP_WAIT(n)  asm volatile("cp.async.wait_group %0;\n" :: "n"(n))

// ---------------- software grid barrier (all NCTA co-resident by launch_bounds) ----
__device__ __forceinline__ void grid_bar()
{
    __syncthreads();
    if (threadIdx.x == 0) {
        __threadfence();
        unsigned gen = *(volatile unsigned*)&g_gen;
        if (atomicAdd(&g_cnt, 1u) == NCTA - 1u) {
            g_cnt = 0u;
            __threadfence();
            atomicAdd(&g_gen, 1u);
        } else {
            while (*(volatile unsigned*)&g_gen == gen) __nanosleep(64);
        }
        __threadfence();
    }
    __syncthreads();
}

// ---------------- shared pool layout ----------------
// dual phase : As  [3][65*24]  at 0      (4680 floats)
//              Bsm [3][2][32*24] at 4680 (4608 floats)  total 9288
// h phase    : As  [3][64*24]  at 0 ; Bs [3][32*24] at 4608
// tagsc phase: sWt [3072] at 0
#define POOL_FLOATS 9288

// ================== persistent mega kernel ==================
__global__ void __launch_bounds__(256, 3) mega_kernel(
    const float* __restrict__ feats, const float* __restrict__ Wd,
    const float* __restrict__ bd,
    const float* __restrict__ Wl, const float* __restrict__ Wr,
    const float* __restrict__ Gl, const float* __restrict__ Gr,
    const float* __restrict__ bl, const float* __restrict__ br,
    const float* __restrict__ bgl, const float* __restrict__ bgr,
    const float* __restrict__ Wt, const float* __restrict__ bt)
{
    __shared__ __align__(16) float pool[POOL_FLOATS];
    const int cta = blockIdx.x;
    const int tid = threadIdx.x;
    const int lane = tid & 31, warp = tid >> 5;
    const int g = lane >> 2, c = lane & 3;

    // ================= phase 0a: prep stacked weights + zero g_ex =================
    {
        int idx = cta * 256 + tid;                 // 0..98303
        if (idx < 65536) {                         // 1024 rows x 16 float4
            int row = idx >> 6, k = (idx & 63) * 4;
            int d = row >> 2, j = row & 3;
            int srcrow = (j == 0) ? d : ((j - 1) * 256 + d);
            const float* sl4 = (j == 0) ? Wl : Gl;
            const float* sr4 = (j == 0) ? Wr : Gr;
            *(float4*)&g_BsL[(size_t)row * 256 + k] = *(const float4*)&sl4[(size_t)srcrow * 256 + k];
            *(float4*)&g_BsR[(size_t)row * 256 + k] = *(const float4*)&sr4[(size_t)srcrow * 256 + k];
        }
        if (idx < 1024) {
            int dd = idx >> 2, jj = idx & 3;
            g_biasS[idx] = (jj == 0) ? (bl[dd] + br[dd])
                                     : (bgl[(jj - 1) * 256 + dd] + bgr[(jj - 1) * 256 + dd]);
        }
        if (idx < L * NT * SPAN) g_ex[idx] = 0.f;
    }

    // ================= phase 0b: h = feats @ Wd^T + bd  (96 CTAs) =================
    if (cta < 96) {
        const int K = 512, NSTEP = 32;
        const int wm = warp & 3, wn = warp >> 2;
        const int m0 = (cta >> 3) * 64, n0 = (cta & 7) * 32;
        const int ar = tid >> 2, ac4 = (tid & 3) * 4;
        const int bi = tid & 127;
        const int brr = bi >> 2, bc4 = (bi & 3) * 4;
        const bool do_b = tid < 128;
        float acc[2][4] = {};

#pragma unroll
        for (int st = 0; st < 2; st++) {
            const int k0 = st * 16;
            cpa16(&pool[st * 1536 + ar * 24 + ac4], &feats[(size_t)(m0 + ar) * K + k0 + ac4]);
            if (do_b) cpa16(&pool[4608 + st * 768 + brr * 24 + bc4],
                            &Wd[(size_t)(n0 + brr) * K + k0 + bc4]);
            CP_COMMIT();
        }
        for (int step = 0; step < NSTEP; step++) {
            const int s = step % 3;
            if (step + 2 < NSTEP) {
                CP_WAIT(1);
                __syncthreads();
                const int k0 = (step + 2) * 16, s2 = (step + 2) % 3;
                cpa16(&pool[s2 * 1536 + ar * 24 + ac4], &feats[(size_t)(m0 + ar) * K + k0 + ac4]);
                if (do_b) cpa16(&pool[4608 + s2 * 768 + brr * 24 + bc4],
                                &Wd[(size_t)(n0 + brr) * K + k0 + bc4]);
                CP_COMMIT();
            } else {
                CP_WAIT(0);
                __syncthreads();
            }
#pragma unroll
            for (int kc = 0; kc < 2; kc++) {
                const int ko = kc * 8 + 2 * c;
                const float* p = &pool[s * 1536 + (wm * 16 + g) * 24 + ko];
                float2 fa0 = *(const float2*)p;
                float2 fa1 = *(const float2*)(p + 8 * 24);
#pragma unroll
                for (int ni = 0; ni < 2; ni++) {
                    const float* pb = &pool[4608 + s * 768 + (wn * 16 + ni * 8 + g) * 24 + ko];
                    float2 fb = *(const float2*)pb;
                    mma_tf32(acc[ni][0], acc[ni][1], acc[ni][2], acc[ni][3],
                             F2U(fa0.x), F2U(fa1.x), F2U(fa0.y), F2U(fa1.y),
                             F2U(fb.x), F2U(fb.y));
                }
            }
        }
#pragma unroll
        for (int ni = 0; ni < 2; ni++) {
            int col = n0 + wn * 16 + ni * 8 + 2 * c;
            float bv0 = bd[col], bv1 = bd[col + 1];
            int row0 = m0 + wm * 16 + g;
            g_ht[0][(size_t)row0 * 256 + col]           = acc[ni][0] + bv0;
            g_ht[0][(size_t)row0 * 256 + col + 1]       = acc[ni][1] + bv1;
            g_ht[0][(size_t)(row0 + 8) * 256 + col]     = acc[ni][2] + bv0;
            g_ht[0][(size_t)(row0 + 8) * 256 + col + 1] = acc[ni][3] + bv1;
        }
    }

    grid_bar();

    // ================= phase 1..7: fused dual GEMM + gate =================
    {
        const int wm = warp & 3, wn = warp >> 2;
        const int m0 = (cta >> 5) * 64, n0 = (cta & 31) * 32;
        const int ar = tid >> 2, ac4 = (tid & 3) * 4;
        const int bh = tid >> 7, bi = tid & 127;
        const int brr = bi >> 2, bc4 = (bi & 3) * 4;
        const float* bsrc = (bh ? g_BsR : g_BsL) + (size_t)n0 * 256;
        const int NSTEP = 16;

        for (int sl = 1; sl <= 7; sl++) {
            const int M = L - sl;
            const float* Aht = g_ht[sl - 1];
            float* htout = g_ht[sl];
            float acc[2][4] = {};

#pragma unroll
            for (int st = 0; st < 2; st++) {
                const int k0 = st * 16;
                cpa16(&pool[st * 1560 + ar * 24 + ac4], &Aht[(size_t)(m0 + ar) * 256 + k0 + ac4]);
                if (tid < 4) cpa16(&pool[st * 1560 + 64 * 24 + tid * 4],
                                   &Aht[(size_t)(m0 + 64) * 256 + k0 + tid * 4]);
                cpa16(&pool[4680 + st * 1536 + bh * 768 + brr * 24 + bc4],
                      &bsrc[(size_t)brr * 256 + k0 + bc4]);
                CP_COMMIT();
            }
            for (int step = 0; step < NSTEP; step++) {
                const int s = step % 3;
                if (step + 2 < NSTEP) {
                    CP_WAIT(1);
                    __syncthreads();
                    const int k0 = (step + 2) * 16, s2 = (step + 2) % 3;
                    cpa16(&pool[s2 * 1560 + ar * 24 + ac4],
                          &Aht[(size_t)(m0 + ar) * 256 + k0 + ac4]);
                    if (tid < 4) cpa16(&pool[s2 * 1560 + 64 * 24 + tid * 4],
                                       &Aht[(size_t)(m0 + 64) * 256 + k0 + tid * 4]);
                    cpa16(&pool[4680 + s2 * 1536 + bh * 768 + brr * 24 + bc4],
                          &bsrc[(size_t)brr * 256 + k0 + bc4]);
                    CP_COMMIT();
                } else {
                    CP_WAIT(0);
                    __syncthreads();
                }
#pragma unroll
                for (int kc = 0; kc < 2; kc++) {
                    const int ko = kc * 8 + 2 * c;
                    const float* p = &pool[s * 1560 + (wm * 16 + g) * 24 + ko];
                    float2 fa0 = *(const float2*)p;
                    float2 fa1 = *(const float2*)(p + 8 * 24);
                    float2 fr0 = *(const float2*)(p + 24);            // shifted row: r
                    float2 fr1 = *(const float2*)(p + 9 * 24);
#pragma unroll
                    for (int ni = 0; ni < 2; ni++) {
                        const int boff = (wn * 16 + ni * 8 + g) * 24 + ko;
                        float2 fbl = *(const float2*)&pool[4680 + s * 1536 + boff];
                        float2 fbr = *(const float2*)&pool[4680 + s * 1536 + 768 + boff];
                        mma_tf32(acc[ni][0], acc[ni][1], acc[ni][2], acc[ni][3],
                                 F2U(fa0.x), F2U(fa1.x), F2U(fa0.y), F2U(fa1.y),
                                 F2U(fbl.x), F2U(fbl.y));
                        mma_tf32(acc[ni][0], acc[ni][1], acc[ni][2], acc[ni][3],
                                 F2U(fr0.x), F2U(fr1.x), F2U(fr0.y), F2U(fr1.y),
                                 F2U(fbr.x), F2U(fbr.y));
                    }
                }
            }
            // ---- fused gate epilogue ----
#pragma unroll
            for (int ni = 0; ni < 2; ni++) {
                int colb = n0 + wn * 16 + ni * 8 + 2 * c;
                float b0 = g_biasS[colb], b1 = g_biasS[colb + 1];
                float z00 = acc[ni][0] + b0, z01 = acc[ni][1] + b1;   // row0
                float z10 = acc[ni][2] + b0, z11 = acc[ni][3] + b1;   // row1
                float w00 = __shfl_xor_sync(0xffffffffu, z00, 1);
                float w01 = __shfl_xor_sync(0xffffffffu, z01, 1);
                float w10 = __shfl_xor_sync(0xffffffffu, z10, 1);
                float w11 = __shfl_xor_sync(0xffffffffu, z11, 1);
                if ((c & 1) == 0) {
                    int d = colb >> 2;
                    int row0 = m0 + wm * 16 + g;
#pragma unroll
                    for (int rr = 0; rr < 2; rr++) {
                        int row = row0 + rr * 8;
                        if (row < M) {
                            float zh  = rr ? z10 : z00;
                            float zg0 = rr ? z11 : z01;
                            float zg1 = rr ? w10 : w00;
                            float zg2 = rr ? w11 : w01;
                            float lft = Aht[(size_t)row * 256 + d];
                            float rgt = Aht[(size_t)(row + 1) * 256 + d];
                            float hh = 4.f / (1.f + __expf(-zh)) - 2.f;
                            float mx = fmaxf(zg0, fmaxf(zg1, zg2));
                            float e0 = __expf(zg0 - mx), e1 = __expf(zg1 - mx),
                                  e2 = __expf(zg2 - mx);
                            float inv = 1.f / (e0 + e1 + e2);
                            htout[(size_t)row * 256 + d] =
                                (e0 * hh + e1 * lft + e2 * rgt) * inv;
                        }
                    }
                }
            }
            grid_bar();
        }
    }

    // ================= phase 8: tag scores + exp gather =================
    {
        for (int i = tid; i < NT * D; i += 256) pool[i] = Wt[i];
        __syncthreads();
#pragma unroll
        for (int rep = 0; rep < 2; rep++) {
            int gw = cta * 8 + warp + rep * 3072;     // 0..6143
            int sl = gw / L;
            int pos = gw - sl * L;
            if (pos + sl < L) {
                const float* hp = g_ht[sl] + (size_t)pos * D;
                float4 h0 = *(const float4*)&hp[lane * 8];
                float4 h1 = *(const float4*)&hp[lane * 8 + 4];
                float hv[8] = {h0.x,h0.y,h0.z,h0.w,h1.x,h1.y,h1.z,h1.w};
                int i_end = pos + sl, kk = 7 - sl;
#pragma unroll
                for (int t = 0; t < NT; t++) {
                    const float* wp = &pool[t * D + lane * 8];
                    float4 w0 = *(const float4*)wp;
                    float4 w1 = *(const float4*)(wp + 4);
                    float s = hv[0]*w0.x + hv[1]*w0.y + hv[2]*w0.z + hv[3]*w0.w
                            + hv[4]*w1.x + hv[5]*w1.y + hv[6]*w1.z + hv[7]*w1.w;
#pragma unroll
                    for (int o = 16; o; o >>= 1) s += __shfl_xor_sync(0xffffffffu, s, o);
                    if (lane == 0) {
                        float val = s + bt[t];
                        g_tagsc[sl][pos * NT + t] = val;
                        g_ex[((size_t)i_end * NT + t) * SPAN + kk] = __expf(val);
                    }
                }
            }
        }
    }
}

// ---------------- gold score + exp-domain forward scan (single warp) ----------------
__global__ void forward_kernel(const float* __restrict__ trans,
                               const float* __restrict__ bt,
                               const int* __restrict__ tags,
                               float* __restrict__ out)
{
    const int lane = threadIdx.x;

    float gold = 0.f;
    for (int s = lane; s < 96; s += 32) {
        int i  = tags[s * 4 + 0];
        int j  = tags[s * 4 + 1];
        int pr = tags[s * 4 + 2];
        int t  = tags[s * 4 + 3];
        int sl = j - i;
        float base;
        if (sl >= 0 && sl < SPAN && i >= 0 && i + sl < L)
            base = g_tagsc[sl][i * NT + t];
        else
            base = bt[t];
        gold += base + trans[pr * NT + t];
    }
#pragma unroll
    for (int o = 16; o; o >>= 1) gold += __shfl_xor_sync(0xffffffffu, gold, o);

    const int t2 = lane < NT ? lane : NT - 1;
    float Texp[NT];
#pragma unroll
    for (int t1 = 0; t1 < NT; t1++) Texp[t1] = expf(trans[t1 * NT + t2]);
    float B[8] = {0.f, 0.f, 0.f, 0.f, 0.f, 0.f, 0.f, Texp[10]};
    float S = 0.f;

    const float4* exbase = (const float4*)(g_ex + (size_t)t2 * SPAN);
    float4 curA[8], curB[8], nxtA[8], nxtB[8];
#pragma unroll
    for (int u = 0; u < 8; u++) {
        curA[u] = exbase[(size_t)u * 24];
        curB[u] = exbase[(size_t)u * 24 + 1];
    }

    float v = 0.f;
    for (int b = 0; b < 96; b++) {
        if (b < 95) {
            const float4* nb = exbase + (size_t)(b + 1) * 8 * 24;
#pragma unroll
            for (int u = 0; u < 8; u++) {
                nxtA[u] = nb[(size_t)u * 24];
                nxtB[u] = nb[(size_t)u * 24 + 1];
            }
        }
#pragma unroll
        for (int u = 0; u < 8; u++) {
            float e0 = curA[u].x, e1 = curA[u].y, e2 = curA[u].z, e3 = curA[u].w;
            float e4 = curB[u].x, e5 = curB[u].y, e6 = curB[u].z, e7 = curB[u].w;
            float v01 = fmaf(e1, B[(u + 1) & 7], e0 * B[(u + 0) & 7]);
            float v23 = fmaf(e3, B[(u + 3) & 7], e2 * B[(u + 2) & 7]);
            float v45 = fmaf(e5, B[(u + 5) & 7], e4 * B[(u + 4) & 7]);
            float v67 = fmaf(e7, B[(u + 7) & 7], e6 * B[(u + 6) & 7]);
            v = (v01 + v23) + (v45 + v67);
            float bnA = 0.f, bnB = 0.f;
#pragma unroll
            for (int t1 = 0; t1 < 6; t1++) {
                bnA = fmaf(Texp[t1],     __shfl_sync(0xffffffffu, v, t1),     bnA);
                bnB = fmaf(Texp[t1 + 6], __shfl_sync(0xffffffffu, v, t1 + 6), bnB);
            }
            B[u] = bnA + bnB;
        }
        if (b < 95) {
            float cc = __shfl_sync(0xffffffffu, v, 0);
            float inv = 1.f / cc;
#pragma unroll
            for (int k = 0; k < 8; k++) B[k] *= inv;
            S += logf(cc);
#pragma unroll
            for (int u = 0; u < 8; u++) { curA[u] = nxtA[u]; curB[u] = nxtB[u]; }
        }
    }

    float contrib = (lane < 11) ? (S + logf(v)) : 0.f;
#pragma unroll
    for (int o = 16; o; o >>= 1) contrib += __shfl_xor_sync(0xffffffffu, contrib, o);
    if (lane == 0) out[0] = contrib - gold;
}

// ---------------- launch ----------------
extern "C" void kernel_launch(void* const* d_in, const int* in_sizes, int n_in,
                              void* d_out, int out_size)
{
    const float* feats = (const float*)d_in[0];
    const int*   tags  = (const int*)d_in[1];
    const float* Wd    = (const float*)d_in[2];
    const float* bd    = (const float*)d_in[3];
    const float* Wl    = (const float*)d_in[4];
    const float* bl    = (const float*)d_in[5];
    const float* Wr    = (const float*)d_in[6];
    const float* br    = (const float*)d_in[7];
    const float* Gl    = (const float*)d_in[8];
    const float* bgl   = (const float*)d_in[9];
    const float* Gr    = (const float*)d_in[10];
    const float* bgr   = (const float*)d_in[11];
    const float* Wt    = (const float*)d_in[12];
    const float* bt    = (const float*)d_in[13];
    const float* trans = (const float*)d_in[14];
    float* out = (float*)d_out;

    mega_kernel<<<NCTA, 256>>>(feats, Wd, bd, Wl, Wr, Gl, Gr,
                               bl, br, bgl, bgr, Wt, bt);
    forward_kernel<<<1, 32>>>(trans, bt, tags, out);
}